// round 4
// baseline (speedup 1.0000x reference)
#include <cuda_runtime.h>
#include <cstdint>

#define B_ 2048
#define S_ 64
#define D_ 512
#define N_ 64
#define A_ 64
#define F_ 512
#define PADA 516      // sA row stride (floats), 16B-divisible
#define PADS 36       // sS row stride
#define PAD2 66       // dup-pair arrays row stride (float2)

typedef unsigned long long u64;

// ---------------- persistent device scratch ------------------------------------
__device__ __align__(16) float g_WvT[F_ * F_];
__device__ __align__(16) float g_ident[N_ * F_];
__device__ __align__(16) float g_k[N_ * F_];
__device__ __align__(16) float g_kq[N_ * D_];
__device__ __align__(16) float g_M1[A_ * F_];
__device__ __align__(16) float g_c1[F_];
__device__ __align__(16) float g_c2[F_];
__device__ __align__(16) float g_c3[F_];
__device__ __align__(16) float g_G2[A_ * A_];
__device__ __align__(16) float g_wb[A_];
__device__ __align__(16) float g_wsum[A_];
__device__ __align__(16) float g_scal[2];

// ---------------- f32x2 helpers --------------------------------------------------
__device__ __forceinline__ u64 fma2(u64 a, u64 b, u64 c) {
    u64 d;
    asm("fma.rn.f32x2 %0, %1, %2, %3;" : "=l"(d) : "l"(a), "l"(b), "l"(c));
    return d;
}
__device__ __forceinline__ u64 dup2(float v) {
    u64 d;
    asm("mov.b64 %0, {%1, %1};" : "=l"(d) : "f"(v));
    return d;
}
__device__ __forceinline__ float2 unpk(u64 v) {
    float2 r;
    asm("mov.b64 {%0, %1}, %2;" : "=f"(r.x), "=f"(r.y) : "l"(v));
    return r;
}

// ---------------- setup 1: Wv transpose + identity encoder ----------------------
__global__ void setup_transpose(const float* __restrict__ Wv,
                                const float* __restrict__ W_ie,
                                const float* __restrict__ b_ie) {
    int t = blockIdx.x * blockDim.x + threadIdx.x;
    int stride = gridDim.x * blockDim.x;
    for (int i = t; i < F_ * F_; i += stride) {
        int g = i >> 9, f = i & 511;
        g_WvT[i] = Wv[f * F_ + g];       // g_WvT[f][go] = Wv[go][f] after relabel
    }
    for (int i = t; i < N_ * F_; i += stride) {
        int n = i >> 9, f = i & 511;
        g_ident[i] = W_ie[f * N_ + n] + b_ie[f];
    }
}

// ---------------- setup 2: k = ident @ Wk^T -------------------------------------
__global__ void setup_k(const float* __restrict__ Wk) {
    int idx = blockIdx.x * blockDim.x + threadIdx.x;
    int n = idx & 63;
    int g = idx >> 6;
    float a0 = 0.f, a1 = 0.f, a2 = 0.f, a3 = 0.f;
#pragma unroll 4
    for (int f = 0; f < F_; f += 4) {
        a0 += g_ident[n * F_ + f + 0] * Wk[g * F_ + f + 0];
        a1 += g_ident[n * F_ + f + 1] * Wk[g * F_ + f + 1];
        a2 += g_ident[n * F_ + f + 2] * Wk[g * F_ + f + 2];
        a3 += g_ident[n * F_ + f + 3] * Wk[g * F_ + f + 3];
    }
    g_k[n * F_ + g] = (a0 + a1) + (a2 + a3);
}

// ---------------- setup 3: kq = scale * k @ Wq -----------------------------------
__global__ void setup_kq(const float* __restrict__ Wq) {
    int d = threadIdx.x;
    int n0 = blockIdx.x * 8;
    float acc[8];
#pragma unroll
    for (int j = 0; j < 8; j++) acc[j] = 0.f;
#pragma unroll 4
    for (int f = 0; f < F_; f++) {
        float wq = Wq[f * D_ + d];
#pragma unroll
        for (int j = 0; j < 8; j++)
            acc[j] += g_k[(n0 + j) * F_ + f] * wq;
    }
    const float scale = 0.04419417382415922f;  // 512^-0.5
#pragma unroll
    for (int j = 0; j < 8; j++)
        g_kq[(n0 + j) * D_ + d] = acc[j] * scale;
}

// ---------------- setup 4: M1 (8 rows/block) + c1,c2,c3 --------------------------
__global__ void setup_M1(const float* __restrict__ W_ae,
                         const float* __restrict__ b_ae,
                         const float* __restrict__ ln_g,
                         const float* __restrict__ ln_b) {
    int t = threadIdx.x;
    int b = blockIdx.x;
    if (b < 8) {
        int al0 = b * 8;
        float acc[8];
#pragma unroll
        for (int j = 0; j < 8; j++) acc[j] = 0.f;
#pragma unroll 4
        for (int f = 0; f < F_; f++) {
            float gw = ln_g[f] * g_WvT[f * 512 + t];
#pragma unroll
            for (int j = 0; j < 8; j++)
                acc[j] += W_ae[f * A_ + al0 + j] * gw;
        }
#pragma unroll
        for (int j = 0; j < 8; j++)
            g_M1[(al0 + j) * 512 + t] = acc[j];
    } else {
        float a1 = 0.f, a2 = 0.f, a3 = 0.f;
#pragma unroll 4
        for (int f = 0; f < F_; f++) {
            float wv = g_WvT[f * 512 + t];
            float gf = ln_g[f];
            a1 += b_ae[f] * gf * wv;
            a2 += gf * wv;
            a3 += ln_b[f] * wv;
        }
        g_c1[t] = a1;
        g_c2[t] = a2;
        g_c3[t] = a3;
    }
}

// ---------------- setup 5: G2, wb, wsum, scalars ----------------------------------
__global__ void setup_G2(const float* __restrict__ W_ae,
                         const float* __restrict__ b_ae) {
    int idx = blockIdx.x * blockDim.x + threadIdx.x;
    if (blockIdx.x < 8) {
        int al = idx & 63, be = idx >> 6;
        float a0 = 0.f, a1 = 0.f, a2 = 0.f, a3 = 0.f;
#pragma unroll 4
        for (int f = 0; f < F_; f += 4) {
            a0 += W_ae[(f + 0) * A_ + al] * W_ae[(f + 0) * A_ + be];
            a1 += W_ae[(f + 1) * A_ + al] * W_ae[(f + 1) * A_ + be];
            a2 += W_ae[(f + 2) * A_ + al] * W_ae[(f + 2) * A_ + be];
            a3 += W_ae[(f + 3) * A_ + al] * W_ae[(f + 3) * A_ + be];
        }
        g_G2[al * A_ + be] = (a0 + a1) + (a2 + a3);
    } else {
        int t = threadIdx.x;
        if (t < 64) {
            float aw = 0.f, as = 0.f;
#pragma unroll 4
            for (int f = 0; f < F_; f++) {
                float w = W_ae[f * A_ + t];
                aw += w * b_ae[f];
                as += w;
            }
            g_wb[t] = aw;
            g_wsum[t] = as;
        } else if (t == 64) {
            float bb = 0.f, sb = 0.f;
            for (int f = 0; f < F_; f++) {
                float v = b_ae[f];
                bb += v * v;
                sb += v;
            }
            g_scal[0] = bb;
            g_scal[1] = sb;
        }
    }
}

// ---------------- fused main kernel: one block per batch -------------------------
__global__ __launch_bounds__(512, 1)
void abind_main_kernel(const float* __restrict__ slots,
                       const float* __restrict__ actions,
                       float* __restrict__ out_slots,   // [B,S,F]
                       float* __restrict__ out_attn)    // [B,N,S]
{
    extern __shared__ float sm[];
    float*  sA     = sm;                                   // 64 x PADA
    float2* sAttn2 = (float2*)(sA + 64 * PADA);            // 64 x PAD2 (dup pairs)
    float2* sAct2  = sAttn2 + 64 * PAD2;                   // 64 x PAD2 (dup pairs)
    float*  sS     = (float*)sAct2;                        // alias: 64 x PADS
    float*  sG2    = (float*)(sAct2 + 64 * PAD2);          // 64 x 64
    float*  sMu    = sG2 + 64 * 64;                        // 64
    float*  sRstd  = sMu + 64;                             // 64

    const int t = threadIdx.x;
    const int b = blockIdx.x;
    const float* slots_b = slots + (size_t)b * S_ * D_;
    const float* act_b   = actions + (size_t)b * N_ * A_;
    float* out1 = out_slots + (size_t)b * S_ * F_;
    float* out2 = out_attn + (size_t)b * N_ * S_;

    // ---- stage kq -> sA (float2), G2 -> sG2 ----
    {
        int half = t >> 8, col = t & 255;
#pragma unroll
        for (int j = 0; j < 32; j++) {
            int row = 2 * j + half;
            *(float2*)&sA[row * PADA + col * 2] =
                *(const float2*)&g_kq[row * 512 + col * 2];
        }
#pragma unroll
        for (int j = 0; j < 8; j++) {
            int i = t + j * 512;
            sG2[i] = g_G2[i];
        }
    }
    __syncthreads();

    // ======== Phase L: logits[n][s] = sum_d kq[n][d] * slots[s][d] ========
    const int sIdx = t & 15, nIdx = t >> 4;     // nIdx 0..31
    const int n0l = nIdx * 2, s0l = sIdx * 4;
    u64 lacc[2][4];
#pragma unroll
    for (int i = 0; i < 2; i++)
#pragma unroll
        for (int j = 0; j < 4; j++) lacc[i][j] = 0ull;

    for (int kc = 0; kc < 16; kc++) {
#pragma unroll
        for (int j = 0; j < 4; j++) {
            int i = t + j * 512;
            int s = i >> 5, d = i & 31;
            sS[s * PADS + d] = slots_b[s * 512 + kc * 32 + d];
        }
        __syncthreads();
        const ulonglong2* pa0 = (const ulonglong2*)&sA[n0l * PADA + kc * 32];
        const ulonglong2* pa1 = (const ulonglong2*)&sA[(n0l + 1) * PADA + kc * 32];
        const ulonglong2* pb0 = (const ulonglong2*)&sS[(s0l + 0) * PADS];
        const ulonglong2* pb1 = (const ulonglong2*)&sS[(s0l + 1) * PADS];
        const ulonglong2* pb2 = (const ulonglong2*)&sS[(s0l + 2) * PADS];
        const ulonglong2* pb3 = (const ulonglong2*)&sS[(s0l + 3) * PADS];
#pragma unroll
        for (int q = 0; q < 8; q++) {
            ulonglong2 a0 = pa0[q], a1 = pa1[q];
            ulonglong2 b0 = pb0[q], b1 = pb1[q], b2 = pb2[q], b3 = pb3[q];
            lacc[0][0] = fma2(a0.x, b0.x, lacc[0][0]);
            lacc[0][0] = fma2(a0.y, b0.y, lacc[0][0]);
            lacc[0][1] = fma2(a0.x, b1.x, lacc[0][1]);
            lacc[0][1] = fma2(a0.y, b1.y, lacc[0][1]);
            lacc[0][2] = fma2(a0.x, b2.x, lacc[0][2]);
            lacc[0][2] = fma2(a0.y, b2.y, lacc[0][2]);
            lacc[0][3] = fma2(a0.x, b3.x, lacc[0][3]);
            lacc[0][3] = fma2(a0.y, b3.y, lacc[0][3]);
            lacc[1][0] = fma2(a1.x, b0.x, lacc[1][0]);
            lacc[1][0] = fma2(a1.y, b0.y, lacc[1][0]);
            lacc[1][1] = fma2(a1.x, b1.x, lacc[1][1]);
            lacc[1][1] = fma2(a1.y, b1.y, lacc[1][1]);
            lacc[1][2] = fma2(a1.x, b2.x, lacc[1][2]);
            lacc[1][2] = fma2(a1.y, b2.y, lacc[1][2]);
            lacc[1][3] = fma2(a1.x, b3.x, lacc[1][3]);
            lacc[1][3] = fma2(a1.y, b3.y, lacc[1][3]);
        }
        __syncthreads();
    }
#pragma unroll
    for (int i = 0; i < 2; i++)
#pragma unroll
        for (int j = 0; j < 4; j++) {
            float2 p = unpk(lacc[i][j]);
            float v = p.x + p.y;
            sAttn2[(n0l + i) * PAD2 + s0l + j] = make_float2(v, v);
        }
    __syncthreads();

    // ======== softmax over s (row n) on dup pairs ========
    if (t < 64) {
        float m = -3.4e38f;
#pragma unroll
        for (int s = 0; s < 64; s++) m = fmaxf(m, sAttn2[t * PAD2 + s].x);
        float sum = 0.f;
        float e[64];
#pragma unroll
        for (int s = 0; s < 64; s++) {
            e[s] = __expf(sAttn2[t * PAD2 + s].x - m);
            sum += e[s];
        }
        float inv = 1.f / sum;
#pragma unroll
        for (int s = 0; s < 64; s++) {
            float v = e[s] * inv;
            sAttn2[t * PAD2 + s] = make_float2(v, v);
        }
    }
    __syncthreads();
    // write attn out; shift dups by EPS for the weighting
#pragma unroll
    for (int j = 0; j < 8; j++) {
        int i = t + j * 512;
        int n = i >> 6, s = i & 63;
        float v = sAttn2[n * PAD2 + s].x;
        out2[i] = v;
        float ve = v + 1e-8f;
        sAttn2[n * PAD2 + s] = make_float2(ve, ve);
    }

    // ---- load actions as dup pairs (overwrites sS alias region) ----
    __syncthreads();
#pragma unroll
    for (int j = 0; j < 8; j++) {
        int i = t + j * 512;
        int n = i >> 6, al = i & 63;
        float v = act_b[i];
        sAct2[n * PAD2 + al] = make_float2(v, v);
    }
    __syncthreads();

    // ======== Stats: mu_n, rstd_n via closed forms ========
    {
        const int n = t >> 3, seg = t & 7;
        float dotj[8];
#pragma unroll
        for (int j = 0; j < 8; j++) dotj[j] = 0.f;
        for (int al = 0; al < 64; al++) {
            float av = sAct2[n * PAD2 + al].x;
#pragma unroll
            for (int j = 0; j < 8; j++)
                dotj[j] += av * sG2[al * 64 + seg * 8 + j];
        }
        float quad = 0.f, wbp = 0.f, wsp = 0.f;
#pragma unroll
        for (int j = 0; j < 8; j++) {
            int be = seg * 8 + j;
            float ab = sAct2[n * PAD2 + be].x;
            quad += ab * dotj[j];
            wbp  += ab * g_wb[be];
            wsp  += ab * g_wsum[be];
        }
#pragma unroll
        for (int o = 1; o < 8; o <<= 1) {
            quad += __shfl_xor_sync(0xffffffffu, quad, o);
            wbp  += __shfl_xor_sync(0xffffffffu, wbp, o);
            wsp  += __shfl_xor_sync(0xffffffffu, wsp, o);
        }
        if (seg == 0) {
            float bb = g_scal[0], sb = g_scal[1];
            float mu = (wsp + sb) * (1.f / 512.f);
            float e2 = (quad + 2.f * wbp + bb) * (1.f / 512.f);
            float var = e2 - mu * mu;
            sMu[n] = mu;
            sRstd[n] = rsqrtf(var + 1e-5f);
        }
    }
    __syncthreads();

    // ======== Phase P: v[n][f] = rs*(act@M1 + c1) - rs*mu*c2 + c3 -> sA ========
    {
        const int fq = t & 127, ng = t >> 7;
        const int f0 = fq * 4, n0 = ng * 16;
        u64 acc[16][2];
        u64 c1a = *(const u64*)&g_c1[f0];
        u64 c1b = *(const u64*)&g_c1[f0 + 2];
#pragma unroll
        for (int n = 0; n < 16; n++) { acc[n][0] = c1a; acc[n][1] = c1b; }

        for (int al2 = 0; al2 < 32; al2++) {
            ulonglong2 w0 = *(const ulonglong2*)&g_M1[(2 * al2) * 512 + f0];
            ulonglong2 w1 = *(const ulonglong2*)&g_M1[(2 * al2 + 1) * 512 + f0];
#pragma unroll
            for (int n = 0; n < 16; n++) {
                ulonglong2 d =
                    *(const ulonglong2*)&sAct2[(n0 + n) * PAD2 + 2 * al2];
                acc[n][0] = fma2(d.x, w0.x, acc[n][0]);
                acc[n][1] = fma2(d.x, w0.y, acc[n][1]);
                acc[n][0] = fma2(d.y, w1.x, acc[n][0]);
                acc[n][1] = fma2(d.y, w1.y, acc[n][1]);
            }
        }
        u64 c2a = *(const u64*)&g_c2[f0];
        u64 c2b = *(const u64*)&g_c2[f0 + 2];
        u64 c3a = *(const u64*)&g_c3[f0];
        u64 c3b = *(const u64*)&g_c3[f0 + 2];
#pragma unroll
        for (int n = 0; n < 16; n++) {
            float rs = sRstd[n0 + n], mu = sMu[n0 + n];
            u64 R = dup2(rs), M = dup2(-rs * mu);
            ulonglong2 st;
            st.x = fma2(R, acc[n][0], fma2(M, c2a, c3a));
            st.y = fma2(R, acc[n][1], fma2(M, c2b, c3b));
            *(ulonglong2*)&sA[(n0 + n) * PADA + f0] = st;
        }
    }
    __syncthreads();

    // ======== Phase T: out[s][f] = sum_n (attn[n][s]+eps) * v[n][f] ========
    {
        const int fq = t & 127, sg = t >> 7;
        const int f0 = fq * 4, s0 = sg * 16;
        u64 acc[16][2];
#pragma unroll
        for (int i = 0; i < 16; i++) { acc[i][0] = 0ull; acc[i][1] = 0ull; }

        for (int n = 0; n < 64; n++) {
            ulonglong2 v = *(const ulonglong2*)&sA[n * PADA + f0];
#pragma unroll
            for (int sp = 0; sp < 8; sp++) {
                ulonglong2 a =
                    *(const ulonglong2*)&sAttn2[n * PAD2 + s0 + 2 * sp];
                acc[2 * sp][0]     = fma2(a.x, v.x, acc[2 * sp][0]);
                acc[2 * sp][1]     = fma2(a.x, v.y, acc[2 * sp][1]);
                acc[2 * sp + 1][0] = fma2(a.y, v.x, acc[2 * sp + 1][0]);
                acc[2 * sp + 1][1] = fma2(a.y, v.y, acc[2 * sp + 1][1]);
            }
        }
#pragma unroll
        for (int i = 0; i < 16; i++) {
            float2 lo = unpk(acc[i][0]), hi = unpk(acc[i][1]);
            float4 o = make_float4(lo.x, lo.y, hi.x, hi.y);
            *(float4*)&out1[(s0 + i) * 512 + f0] = o;
        }
    }
}

// ---------------- launch ----------------------------------------------------------
extern "C" void kernel_launch(void* const* d_in, const int* in_sizes, int n_in,
                              void* d_out, int out_size) {
    const float* slots   = (const float*)d_in[0];
    const float* actions = (const float*)d_in[1];
    const float* W_ae    = (const float*)d_in[2];
    const float* b_ae    = (const float*)d_in[3];
    const float* W_ie    = (const float*)d_in[4];
    const float* b_ie    = (const float*)d_in[5];
    const float* ln_g    = (const float*)d_in[6];
    const float* ln_b    = (const float*)d_in[7];
    const float* Wq      = (const float*)d_in[8];
    const float* Wk      = (const float*)d_in[9];
    const float* Wv      = (const float*)d_in[10];

    float* out      = (float*)d_out;
    float* out_attn = out + (size_t)B_ * S_ * F_;

    setup_transpose<<<256, 256>>>(Wv, W_ie, b_ie);
    setup_k<<<64, 512>>>(Wk);
    setup_kq<<<8, 512>>>(Wq);
    setup_M1<<<9, 512>>>(W_ae, b_ae, ln_g, ln_b);
    setup_G2<<<9, 512>>>(W_ae, b_ae);

    const size_t SMEM =
        (64 * PADA + 64 * PAD2 * 2 * 2 + 64 * 64 + 128) * sizeof(float);
    cudaFuncSetAttribute(abind_main_kernel,
                         cudaFuncAttributeMaxDynamicSharedMemorySize, (int)SMEM);
    abind_main_kernel<<<B_, 512, SMEM>>>(slots, actions, out, out_attn);
}

// round 6
// speedup vs baseline: 1.2626x; 1.2626x over previous
#include <cuda_runtime.h>
#include <cstdint>

#define B_ 2048
#define S_ 64
#define D_ 512
#define N_ 64
#define A_ 64
#define F_ 512

typedef unsigned long long u64;

// ---------------- persistent device scratch ------------------------------------
__device__ __align__(16) float g_WvT[F_ * F_];
__device__ __align__(16) float g_ident[N_ * F_];
__device__ __align__(16) float g_k[N_ * F_];
__device__ __align__(16) float g_kq[N_ * D_];
__device__ __align__(16) float g_M1[A_ * F_];
__device__ __align__(16) float g_c1[F_];
__device__ __align__(16) float g_c2[F_];
__device__ __align__(16) float g_c3[F_];
__device__ __align__(16) float g_G2[A_ * A_];
__device__ __align__(16) float g_wb[A_];
__device__ __align__(16) float g_wsum[A_];
__device__ __align__(16) float g_scal[2];
__device__ __align__(16) float g_stats[B_ * 2 * N_];          // (mu, rstd) per (b,n)
__device__ __align__(16) float g_attnE2[(size_t)B_ * N_ * S_ * 2];  // dup pairs, 64MB

// ---------------- f32x2 helpers --------------------------------------------------
__device__ __forceinline__ u64 fma2(u64 a, u64 b, u64 c) {
    u64 d;
    asm("fma.rn.f32x2 %0, %1, %2, %3;" : "=l"(d) : "l"(a), "l"(b), "l"(c));
    return d;
}
__device__ __forceinline__ u64 dup2(float v) {
    u64 d;
    asm("mov.b64 %0, {%1, %1};" : "=l"(d) : "f"(v));
    return d;
}
__device__ __forceinline__ float2 unpk(u64 v) {
    float2 r;
    asm("mov.b64 {%0, %1}, %2;" : "=f"(r.x), "=f"(r.y) : "l"(v));
    return r;
}

// ---------------- setup 1: Wv transpose + identity encoder ----------------------
__global__ void setup_transpose(const float* __restrict__ Wv,
                                const float* __restrict__ W_ie,
                                const float* __restrict__ b_ie) {
    int t = blockIdx.x * blockDim.x + threadIdx.x;
    int stride = gridDim.x * blockDim.x;
    for (int i = t; i < F_ * F_; i += stride) {
        int g = i >> 9, f = i & 511;
        g_WvT[i] = Wv[f * F_ + g];      // g_WvT[f][go] = Wv[go][f] after relabel
    }
    for (int i = t; i < N_ * F_; i += stride) {
        int n = i >> 9, f = i & 511;
        g_ident[i] = W_ie[f * N_ + n] + b_ie[f];
    }
}

// ---------------- setup 2: k = ident @ Wk^T --------------------------------------
__global__ void setup_k(const float* __restrict__ Wk) {
    int idx = blockIdx.x * blockDim.x + threadIdx.x;
    int n = idx & 63;
    int g = idx >> 6;
    float a0 = 0.f, a1 = 0.f, a2 = 0.f, a3 = 0.f;
#pragma unroll 4
    for (int f = 0; f < F_; f += 4) {
        a0 += g_ident[n * F_ + f + 0] * Wk[g * F_ + f + 0];
        a1 += g_ident[n * F_ + f + 1] * Wk[g * F_ + f + 1];
        a2 += g_ident[n * F_ + f + 2] * Wk[g * F_ + f + 2];
        a3 += g_ident[n * F_ + f + 3] * Wk[g * F_ + f + 3];
    }
    g_k[n * F_ + g] = (a0 + a1) + (a2 + a3);
}

// ---------------- setup 3: kq = scale * k @ Wq  (grid 8x8, 64 thr) ---------------
__global__ void setup_kq(const float* __restrict__ Wq) {
    int d = blockIdx.y * 64 + threadIdx.x;
    int n0 = blockIdx.x * 8;
    float acc[8];
#pragma unroll
    for (int j = 0; j < 8; j++) acc[j] = 0.f;
#pragma unroll 4
    for (int f = 0; f < F_; f++) {
        float wq = Wq[f * D_ + d];
#pragma unroll
        for (int j = 0; j < 8; j++)
            acc[j] += g_k[(n0 + j) * F_ + f] * wq;
    }
    const float scale = 0.04419417382415922f;  // 512^-0.5
#pragma unroll
    for (int j = 0; j < 8; j++)
        g_kq[(n0 + j) * D_ + d] = acc[j] * scale;
}

// ---------------- setup 4: M1 rows + c1,c2,c3 (grid 67, K-ILP4) -------------------
__global__ void setup_M1(const float* __restrict__ W_ae,
                         const float* __restrict__ b_ae,
                         const float* __restrict__ ln_g,
                         const float* __restrict__ ln_b) {
    int t = threadIdx.x;
    int b = blockIdx.x;
    if (b < 64) {
        float a0 = 0.f, a1 = 0.f, a2 = 0.f, a3 = 0.f;
#pragma unroll 2
        for (int f = 0; f < F_; f += 4) {
            a0 += W_ae[(f + 0) * A_ + b] * ln_g[f + 0] * g_WvT[(f + 0) * 512 + t];
            a1 += W_ae[(f + 1) * A_ + b] * ln_g[f + 1] * g_WvT[(f + 1) * 512 + t];
            a2 += W_ae[(f + 2) * A_ + b] * ln_g[f + 2] * g_WvT[(f + 2) * 512 + t];
            a3 += W_ae[(f + 3) * A_ + b] * ln_g[f + 3] * g_WvT[(f + 3) * 512 + t];
        }
        g_M1[b * 512 + t] = (a0 + a1) + (a2 + a3);
    } else if (b == 64) {
        float a0 = 0.f, a1 = 0.f;
#pragma unroll 2
        for (int f = 0; f < F_; f += 2) {
            a0 += b_ae[f] * ln_g[f] * g_WvT[f * 512 + t];
            a1 += b_ae[f + 1] * ln_g[f + 1] * g_WvT[(f + 1) * 512 + t];
        }
        g_c1[t] = a0 + a1;
    } else if (b == 65) {
        float a0 = 0.f, a1 = 0.f;
#pragma unroll 2
        for (int f = 0; f < F_; f += 2) {
            a0 += ln_g[f] * g_WvT[f * 512 + t];
            a1 += ln_g[f + 1] * g_WvT[(f + 1) * 512 + t];
        }
        g_c2[t] = a0 + a1;
    } else {
        float a0 = 0.f, a1 = 0.f;
#pragma unroll 2
        for (int f = 0; f < F_; f += 2) {
            a0 += ln_b[f] * g_WvT[f * 512 + t];
            a1 += ln_b[f + 1] * g_WvT[(f + 1) * 512 + t];
        }
        g_c3[t] = a0 + a1;
    }
}

// ---------------- setup 5: G2, wb, wsum, scalars ----------------------------------
__global__ void setup_G2(const float* __restrict__ W_ae,
                         const float* __restrict__ b_ae) {
    int idx = blockIdx.x * blockDim.x + threadIdx.x;
    if (blockIdx.x < 8) {
        int al = idx & 63, be = idx >> 6;
        float a0 = 0.f, a1 = 0.f, a2 = 0.f, a3 = 0.f;
#pragma unroll 4
        for (int f = 0; f < F_; f += 4) {
            a0 += W_ae[(f + 0) * A_ + al] * W_ae[(f + 0) * A_ + be];
            a1 += W_ae[(f + 1) * A_ + al] * W_ae[(f + 1) * A_ + be];
            a2 += W_ae[(f + 2) * A_ + al] * W_ae[(f + 2) * A_ + be];
            a3 += W_ae[(f + 3) * A_ + al] * W_ae[(f + 3) * A_ + be];
        }
        g_G2[al * A_ + be] = (a0 + a1) + (a2 + a3);
    } else {
        int t = threadIdx.x;
        if (t < 64) {
            float aw = 0.f, as = 0.f;
#pragma unroll 4
            for (int f = 0; f < F_; f++) {
                float w = W_ae[f * A_ + t];
                aw += w * b_ae[f];
                as += w;
            }
            g_wb[t] = aw;
            g_wsum[t] = as;
        } else if (t == 64) {
            float bb = 0.f, sb = 0.f;
            for (int f = 0; f < F_; f++) {
                float v = b_ae[f];
                bb += v * v;
                sb += v;
            }
            g_scal[0] = bb;
            g_scal[1] = sb;
        }
    }
}

// =================== kernel C: LN stats per (b,n) =================================
__global__ __launch_bounds__(256)
void stats_kernel(const float* __restrict__ actions) {
    __shared__ float sAct[64 * 65];
    __shared__ float sG2s[64 * 64];
    __shared__ float sWb[64], sWs[64];
    const int t = threadIdx.x;
    const int b = blockIdx.x;
    const float* act_b = actions + (size_t)b * N_ * A_;

#pragma unroll
    for (int j = 0; j < 16; j++) {
        int i = t + j * 256;
        sAct[(i >> 6) * 65 + (i & 63)] = act_b[i];
        sG2s[i] = g_G2[i];
    }
    if (t < 64) { sWb[t] = g_wb[t]; sWs[t] = g_wsum[t]; }
    __syncthreads();

    const int n = t >> 2, seg = t & 3;     // 16 beta cols per thread
    float dotj[16];
#pragma unroll
    for (int j = 0; j < 16; j++) dotj[j] = 0.f;
    for (int al = 0; al < 64; al++) {
        float av = sAct[n * 65 + al];
        const float4* g4 = (const float4*)&sG2s[al * 64 + seg * 16];
#pragma unroll
        for (int q = 0; q < 4; q++) {
            float4 g = g4[q];
            dotj[q * 4 + 0] += av * g.x;
            dotj[q * 4 + 1] += av * g.y;
            dotj[q * 4 + 2] += av * g.z;
            dotj[q * 4 + 3] += av * g.w;
        }
    }
    float quad = 0.f, wbp = 0.f, wsp = 0.f;
#pragma unroll
    for (int j = 0; j < 16; j++) {
        int be = seg * 16 + j;
        float ab = sAct[n * 65 + be];
        quad += ab * dotj[j];
        wbp += ab * sWb[be];
        wsp += ab * sWs[be];
    }
#pragma unroll
    for (int o = 1; o < 4; o <<= 1) {
        quad += __shfl_xor_sync(0xffffffffu, quad, o);
        wbp  += __shfl_xor_sync(0xffffffffu, wbp, o);
        wsp  += __shfl_xor_sync(0xffffffffu, wsp, o);
    }
    if (seg == 0) {
        float bb = g_scal[0], sb = g_scal[1];
        float mu = (wsp + sb) * (1.f / 512.f);
        float e2 = (quad + 2.f * wbp + bb) * (1.f / 512.f);
        float var = e2 - mu * mu;
        g_stats[b * 128 + 2 * n]     = mu;
        g_stats[b * 128 + 2 * n + 1] = rsqrtf(var + 1e-5f);
    }
}

// =================== kernel A: logits + softmax -> attn, attnE2 ==================
__global__ __launch_bounds__(256)
void attn_kernel(const float* __restrict__ slots, float* __restrict__ out_attn) {
    __shared__ float2 sKq2[64 * 64];    // [n][d-chunk] dup pairs, 32KB
    __shared__ float  sSlT[64 * 68];    // [d][s] transposed chunk, 17.4KB
    const int t = threadIdx.x;
    const int b = blockIdx.x;
    const float* slots_b = slots + (size_t)b * S_ * D_;
    const int nI = t >> 3, sI = t & 7;
    const int n0 = nI * 2, s0 = sI * 8;

    u64 acc[2][4];
#pragma unroll
    for (int i = 0; i < 2; i++)
#pragma unroll
        for (int j = 0; j < 4; j++) acc[i][j] = 0ull;

    for (int dc = 0; dc < 8; dc++) {
        if (dc) __syncthreads();
#pragma unroll
        for (int j = 0; j < 16; j++) {
            int i = t + j * 256;
            int n = i >> 6, d = i & 63;
            float v = g_kq[n * 512 + dc * 64 + d];
            sKq2[n * 64 + d] = make_float2(v, v);
        }
#pragma unroll
        for (int j = 0; j < 4; j++) {
            int i = t + j * 256;
            int s = i >> 4, q = i & 15;
            float4 v = *(const float4*)&slots_b[s * 512 + dc * 64 + q * 4];
            sSlT[(q * 4 + 0) * 68 + s] = v.x;
            sSlT[(q * 4 + 1) * 68 + s] = v.y;
            sSlT[(q * 4 + 2) * 68 + s] = v.z;
            sSlT[(q * 4 + 3) * 68 + s] = v.w;
        }
        __syncthreads();

        const ulonglong2* kq0 = (const ulonglong2*)&sKq2[n0 * 64];
        const ulonglong2* kq1 = (const ulonglong2*)&sKq2[(n0 + 1) * 64];
#pragma unroll
        for (int d2 = 0; d2 < 32; d2++) {
            ulonglong2 k0 = kq0[d2];
            ulonglong2 k1 = kq1[d2];
            ulonglong2 sa = *(const ulonglong2*)&sSlT[(2 * d2) * 68 + s0];
            ulonglong2 sb = *(const ulonglong2*)&sSlT[(2 * d2) * 68 + s0 + 4];
            ulonglong2 sc = *(const ulonglong2*)&sSlT[(2 * d2 + 1) * 68 + s0];
            ulonglong2 sd = *(const ulonglong2*)&sSlT[(2 * d2 + 1) * 68 + s0 + 4];
            acc[0][0] = fma2(k0.x, sa.x, acc[0][0]);
            acc[0][1] = fma2(k0.x, sa.y, acc[0][1]);
            acc[0][2] = fma2(k0.x, sb.x, acc[0][2]);
            acc[0][3] = fma2(k0.x, sb.y, acc[0][3]);
            acc[1][0] = fma2(k1.x, sa.x, acc[1][0]);
            acc[1][1] = fma2(k1.x, sa.y, acc[1][1]);
            acc[1][2] = fma2(k1.x, sb.x, acc[1][2]);
            acc[1][3] = fma2(k1.x, sb.y, acc[1][3]);
            acc[0][0] = fma2(k0.y, sc.x, acc[0][0]);
            acc[0][1] = fma2(k0.y, sc.y, acc[0][1]);
            acc[0][2] = fma2(k0.y, sd.x, acc[0][2]);
            acc[0][3] = fma2(k0.y, sd.y, acc[0][3]);
            acc[1][0] = fma2(k1.y, sc.x, acc[1][0]);
            acc[1][1] = fma2(k1.y, sc.y, acc[1][1]);
            acc[1][2] = fma2(k1.y, sd.x, acc[1][2]);
            acc[1][3] = fma2(k1.y, sd.y, acc[1][3]);
        }
    }

    // register softmax across the 8 lanes sharing each n-row (lanes sI=0..7)
    float* o2 = out_attn + (size_t)b * N_ * S_;
    float* gE = g_attnE2 + (size_t)b * 8192;
#pragma unroll
    for (int i = 0; i < 2; i++) {
        float l[8];
#pragma unroll
        for (int j = 0; j < 4; j++) {
            float2 p = unpk(acc[i][j]);
            l[2 * j] = p.x;
            l[2 * j + 1] = p.y;
        }
        float m = l[0];
#pragma unroll
        for (int j = 1; j < 8; j++) m = fmaxf(m, l[j]);
#pragma unroll
        for (int o = 1; o < 8; o <<= 1) m = fmaxf(m, __shfl_xor_sync(0xffffffffu, m, o));
        float sum = 0.f;
#pragma unroll
        for (int j = 0; j < 8; j++) {
            l[j] = __expf(l[j] - m);
            sum += l[j];
        }
#pragma unroll
        for (int o = 1; o < 8; o <<= 1) sum += __shfl_xor_sync(0xffffffffu, sum, o);
        float inv = 1.f / sum;
#pragma unroll
        for (int j = 0; j < 8; j++) l[j] *= inv;

        int n = n0 + i;
        *(float4*)&o2[n * 64 + s0]     = make_float4(l[0], l[1], l[2], l[3]);
        *(float4*)&o2[n * 64 + s0 + 4] = make_float4(l[4], l[5], l[6], l[7]);
        float e0 = l[0] + 1e-8f, e1 = l[1] + 1e-8f, e2v = l[2] + 1e-8f, e3 = l[3] + 1e-8f;
        float e4 = l[4] + 1e-8f, e5 = l[5] + 1e-8f, e6 = l[6] + 1e-8f, e7 = l[7] + 1e-8f;
        float4* gd = (float4*)&gE[n * 128 + s0 * 2];
        gd[0] = make_float4(e0, e0, e1, e1);
        gd[1] = make_float4(e2v, e2v, e3, e3);
        gd[2] = make_float4(e4, e4, e5, e5);
        gd[3] = make_float4(e6, e6, e7, e7);
    }
}

// =================== kernel B: P (act@M1 + LN affine) + T (attnE @ v) ============
// grid (2048, 2): blockIdx.y = f-half (256 cols). 256 threads, occ 2.
#define BSM_FLOATS (64 * 256 + 64 * 66 * 2 + 128)
__global__ __launch_bounds__(256, 2)
void bind_kernel(const float* __restrict__ actions,
                 float* __restrict__ out_slots) {
    extern __shared__ float bsm[];
    float*  sV     = bsm;                           // 64 x 256
    float2* sAct2  = (float2*)(bsm + 64 * 256);     // 64 x 66 dup pairs (33.8KB)
    float4* sStage = (float4*)sAct2;                // alias for attnE2 chunks
    float*  sStats = bsm + 64 * 256 + 64 * 66 * 2;  // 128

    const int t = threadIdx.x;
    const int b = blockIdx.x;
    const int fy = blockIdx.y;
    const float* act_b = actions + (size_t)b * N_ * A_;

#pragma unroll
    for (int j = 0; j < 16; j++) {
        int i = t + j * 256;
        int n = i >> 6, al = i & 63;
        float v = act_b[i];
        sAct2[n * 66 + al] = make_float2(v, v);
    }
    if (t < 128) sStats[t] = g_stats[b * 128 + t];
    __syncthreads();

    // ---- Phase P: v[n][f-pair] into sV ----
    {
        const int fp = t & 127, ng = t >> 7;
        const int n0 = ng * 32;
        const int fbase = fy * 256 + fp * 2;
        u64 acc[32];
        u64 c1p = *(const u64*)&g_c1[fbase];
#pragma unroll
        for (int n = 0; n < 32; n++) acc[n] = c1p;

        for (int al2 = 0; al2 < 32; al2++) {
            u64 w0 = *(const u64*)&g_M1[(2 * al2) * 512 + fbase];
            u64 w1 = *(const u64*)&g_M1[(2 * al2 + 1) * 512 + fbase];
#pragma unroll
            for (int n4 = 0; n4 < 8; n4++) {
                ulonglong2 a0 = *(const ulonglong2*)&sAct2[(n0 + n4 * 4 + 0) * 66 + 2 * al2];
                ulonglong2 a1 = *(const ulonglong2*)&sAct2[(n0 + n4 * 4 + 1) * 66 + 2 * al2];
                ulonglong2 a2 = *(const ulonglong2*)&sAct2[(n0 + n4 * 4 + 2) * 66 + 2 * al2];
                ulonglong2 a3 = *(const ulonglong2*)&sAct2[(n0 + n4 * 4 + 3) * 66 + 2 * al2];
                acc[n4 * 4 + 0] = fma2(a0.x, w0, acc[n4 * 4 + 0]);
                acc[n4 * 4 + 1] = fma2(a1.x, w0, acc[n4 * 4 + 1]);
                acc[n4 * 4 + 2] = fma2(a2.x, w0, acc[n4 * 4 + 2]);
                acc[n4 * 4 + 3] = fma2(a3.x, w0, acc[n4 * 4 + 3]);
                acc[n4 * 4 + 0] = fma2(a0.y, w1, acc[n4 * 4 + 0]);
                acc[n4 * 4 + 1] = fma2(a1.y, w1, acc[n4 * 4 + 1]);
                acc[n4 * 4 + 2] = fma2(a2.y, w1, acc[n4 * 4 + 2]);
                acc[n4 * 4 + 3] = fma2(a3.y, w1, acc[n4 * 4 + 3]);
            }
        }
        u64 c2p = *(const u64*)&g_c2[fbase];
        u64 c3p = *(const u64*)&g_c3[fbase];
#pragma unroll
        for (int n = 0; n < 32; n++) {
            float mu = sStats[2 * (n0 + n)], rs = sStats[2 * (n0 + n) + 1];
            u64 v = fma2(dup2(rs), acc[n], fma2(dup2(-rs * mu), c2p, c3p));
            *(u64*)&sV[(n0 + n) * 256 + fp * 2] = v;
        }
    }
    __syncthreads();

    // ---- Phase T: out[s][f-pair] = sum_n eDup(n,s) * vPair(n,f) ----
    {
        const int fp = t & 127;          // f-pair within the 256-col window
        const int sg = t >> 7;           // s half: 0 -> s 0..31, 1 -> s 32..63
        u64 tacc[32];
#pragma unroll
        for (int i = 0; i < 32; i++) tacc[i] = 0ull;

        const float4* gE4 = (const float4*)(g_attnE2 + (size_t)b * 8192);
        for (int nc = 0; nc < 8; nc++) {
            __syncthreads();
            sStage[t] = gE4[nc * 256 + t];     // 8 n-rows x 128 floats
            __syncthreads();
            const float* stF = (const float*)sStage;
#pragma unroll
            for (int nl = 0; nl < 8; nl++) {
                int n = nc * 8 + nl;
                u64 vp = *(const u64*)&sV[n * 256 + 2 * fp];
                const ulonglong2* ap =
                    (const ulonglong2*)(stF + nl * 128 + sg * 64);
#pragma unroll
                for (int j = 0; j < 16; j++) {
                    ulonglong2 a = ap[j];     // dup(e_{2j}), dup(e_{2j+1})
                    tacc[2 * j]     = fma2(a.x, vp, tacc[2 * j]);
                    tacc[2 * j + 1] = fma2(a.y, vp, tacc[2 * j + 1]);
                }
            }
        }
        float* o1 = out_slots + (size_t)b * S_ * F_ + fy * 256;
#pragma unroll
        for (int sl = 0; sl < 32; sl++) {
            int s = sg * 32 + sl;
            float2 p = unpk(tacc[sl]);
            *(float2*)&o1[s * 512 + 2 * fp] = p;
        }
    }
}

// ---------------- launch ----------------------------------------------------------
extern "C" void kernel_launch(void* const* d_in, const int* in_sizes, int n_in,
                              void* d_out, int out_size) {
    const float* slots   = (const float*)d_in[0];
    const float* actions = (const float*)d_in[1];
    const float* W_ae    = (const float*)d_in[2];
    const float* b_ae    = (const float*)d_in[3];
    const float* W_ie    = (const float*)d_in[4];
    const float* b_ie    = (const float*)d_in[5];
    const float* ln_g    = (const float*)d_in[6];
    const float* ln_b    = (const float*)d_in[7];
    const float* Wq      = (const float*)d_in[8];
    const float* Wk      = (const float*)d_in[9];
    const float* Wv      = (const float*)d_in[10];

    float* out      = (float*)d_out;
    float* out_attn = out + (size_t)B_ * S_ * F_;

    setup_transpose<<<256, 256>>>(Wv, W_ie, b_ie);
    setup_k<<<64, 512>>>(Wk);
    setup_kq<<<dim3(8, 8), 64>>>(Wq);
    setup_M1<<<67, 512>>>(W_ae, b_ae, ln_g, ln_b);
    setup_G2<<<9, 512>>>(W_ae, b_ae);

    stats_kernel<<<B_, 256>>>(actions);
    attn_kernel<<<B_, 256>>>(slots, out_attn);

    const size_t BSM = BSM_FLOATS * sizeof(float);
    cudaFuncSetAttribute(bind_kernel,
                         cudaFuncAttributeMaxDynamicSharedMemorySize, (int)BSM);
    bind_kernel<<<dim3(B_, 2), 256, BSM>>>(actions, out);
}